// round 11
// baseline (speedup 1.0000x reference)
#include <cuda_runtime.h>
#include <math.h>
#include <stdint.h>

#define NTOT 32768
#define HTOT 32
#define D    64
#define NT   128
#define NTHREADS 256
#define TILE_BYTES (NT * D * 4)   // 32768

// ---------- tf32 helpers ----------
__device__ __forceinline__ uint32_t f2tf32(float f) {
    uint32_t u;
    asm("cvt.rna.tf32.f32 %0, %1;" : "=r"(u) : "f"(f));
    return u;
}

__device__ __forceinline__ void mma_tf32(float& c0, float& c1, float& c2, float& c3,
                                         uint32_t a0, uint32_t a1, uint32_t a2, uint32_t a3,
                                         uint32_t b0, uint32_t b1) {
    asm volatile(
        "mma.sync.aligned.m16n8k8.row.col.f32.tf32.tf32.f32 "
        "{%0,%1,%2,%3}, {%4,%5,%6,%7}, {%8,%9}, {%0,%1,%2,%3};"
        : "+f"(c0), "+f"(c1), "+f"(c2), "+f"(c3)
        : "r"(a0), "r"(a1), "r"(a2), "r"(a3), "r"(b0), "r"(b1));
}

__device__ __forceinline__ float poly_tanh(float x) {
    float t = x * x;
    float p = fmaf(t, -0.05396825397f, 0.13333333333f);
    p = fmaf(t, p, -0.33333333333f);
    return fmaf(x * t, p, x);
}

__device__ __forceinline__ float logscale_from_ssq(float ssq, float c) {
    float t = c * ssq;
    float p = fmaf(t, 0.22222222f, 0.28571429f);
    p = fmaf(t, p, 0.4f);
    p = fmaf(t, p, 0.66666667f);
    return fmaf(t, p, 2.0f);
}

// Fragment-native swizzled tile layout (conflict-free; rounds 3-9).
__device__ __forceinline__ int chunk_off(int token, int ci, int j) {
    int pb = (token >> 1) & 1;
    int b2 = (token >> 2) & 1;
    int jl = j & 1;
    int j1 = (j >> 1) & 1;
    int slot = ((token & 1) << 2) | (ci ^ (jl ^ pb) ^ ((j1 ^ b2) << 1));
    return ((token >> 1) << 7) | (j << 5) | (slot << 2);
}

// ---------- TMA bulk copy + mbarrier (proven rounds 7-9) ----------
__device__ __forceinline__ void mbar_init(uint32_t mbar, uint32_t cnt) {
    asm volatile("mbarrier.init.shared.b64 [%0], %1;" :: "r"(mbar), "r"(cnt) : "memory");
}
__device__ __forceinline__ void mbar_expect_tx(uint32_t mbar, uint32_t bytes) {
    asm volatile("mbarrier.arrive.expect_tx.shared.b64 _, [%0], %1;"
                 :: "r"(mbar), "r"(bytes) : "memory");
}
__device__ __forceinline__ void bulk_ld(uint32_t sdst, const void* gsrc, uint32_t mbar) {
    asm volatile(
        "cp.async.bulk.shared::cta.global.mbarrier::complete_tx::bytes [%0], [%1], %2, [%3];"
        :: "r"(sdst), "l"(gsrc), "r"((uint32_t)TILE_BYTES), "r"(mbar) : "memory");
}
__device__ __forceinline__ void mbar_wait(uint32_t mbar, uint32_t parity) {
    uint32_t done;
    asm volatile(
        "{\n\t.reg .pred p;\n\t"
        "mbarrier.try_wait.parity.acquire.cta.shared::cta.b64 p, [%1], %2;\n\t"
        "selp.b32 %0, 1, 0, p;\n\t}"
        : "=r"(done) : "r"(mbar), "r"(parity) : "memory");
    if (!done) {
        asm volatile(
            "{\n\t.reg .pred P1;\n\t"
            "WAIT_LOOP_%=:\n\t"
            "mbarrier.try_wait.parity.acquire.cta.shared::cta.b64 P1, [%0], %1, 0x989680;\n\t"
            "@P1 bra.uni WAIT_DONE_%=;\n\t"
            "bra.uni WAIT_LOOP_%=;\n\t"
            "WAIT_DONE_%=:\n\t}"
            :: "r"(mbar), "r"(parity) : "memory");
    }
}

// 256-thread transform (proven round 9): rows rgrp + 16*jj, jj = 0..7
__device__ __forceinline__ void transform_tile(const float* __restrict__ stag,
                                               uint32_t* __restrict__ tileU,
                                               int pt, float c) {
    const float4* s4 = reinterpret_cast<const float4*>(stag);
    const int col4 = pt & 15;
    const int rgrp = pt >> 4;         // 0..15
    const int j    = col4 >> 2;
    const int posR = col4 & 3;
    const int posP = posR ^ ((j & 1) << 1);
    int base[4];
    #pragma unroll
    for (int ci = 0; ci < 4; ci++)
        base[ci] = chunk_off(rgrp, ci, j) + posP;

    #pragma unroll
    for (int jj = 0; jj < 8; jj++) {
        float4 v = s4[pt + 256 * jj];
        float s = fmaf(v.x, v.x, fmaf(v.y, v.y, fmaf(v.z, v.z, v.w * v.w)));
        #pragma unroll
        for (int off = 1; off < 16; off <<= 1)
            s += __shfl_xor_sync(0xffffffffu, s, off);
        float sc = logscale_from_ssq(s, c);
        int o = jj << 10;             // +16 rows = +1024 floats
        tileU[base[0] + o] = f2tf32(v.x * sc);
        tileU[base[1] + o] = f2tf32(v.y * sc);
        tileU[base[2] + o] = f2tf32(v.z * sc);
        tileU[base[3] + o] = f2tf32(v.w * sc);
    }
}

__global__ __launch_bounds__(NTHREADS, 1)
void hyp_attn_kernel(const float* __restrict__ cur,
                     const float* __restrict__ hist,
                     const float* __restrict__ curv,
                     const float* __restrict__ Wq,
                     const float* __restrict__ bq,
                     const float* __restrict__ Wk,
                     const float* __restrict__ bk,
                     const float* __restrict__ av,
                     float* __restrict__ out) {
    extern __shared__ float sm[];
    uint32_t* tileU = reinterpret_cast<uint32_t*>(sm);   // 8192 u32
    float* stagA = sm + 8192;                            // 8192
    float* stagB = sm + 16384;                           // 8192
    float4* qfS  = reinterpret_cast<float4*>(sm + 24576);// 2048 float4
    float* avS   = sm + 32768;                           // 64
    uint32_t mbarBase = (uint32_t)__cvta_generic_to_shared(sm + 32832);

    const int t    = threadIdx.x;
    const int lane = t & 31;
    const int w    = t >> 5;          // 0..7 : token group
    const int n0   = blockIdx.x * NT;
    const float c  = curv[0];

    const uint32_t mbar0 = mbarBase;
    const uint32_t mbar1 = mbarBase + 8;
    const uint32_t stAu = (uint32_t)__cvta_generic_to_shared(stagA);
    const uint32_t stBu = (uint32_t)__cvta_generic_to_shared(stagB);

    const int Tg = w * 16;
    const int lr = lane >> 2;         // 0..7
    const int ci = lane & 3;

    // A-fragment bases for token Tg+lr (token +8 is +512)
    int fbA[4];
    #pragma unroll
    for (int j = 0; j < 4; j++) fbA[j] = chunk_off(Tg + lr, ci, j);

    // warp-local RMW ownership: lane owns token Tm, d-half hh
    const int Tm = Tg + (lane >> 1);
    const int hh = lane & 1;
    int roff[2][4];
    #pragma unroll
    for (int jj = 0; jj < 2; jj++)
        #pragma unroll
        for (int cc = 0; cc < 4; cc++)
            roff[jj][cc] = chunk_off(Tm, cc, 2 * hh + jj);

    // ---- TMA: first load (current tile) ----
    if (t == 0) {
        mbar_init(mbar0, 1);
        mbar_init(mbar1, 1);
        asm volatile("fence.proxy.async.shared::cta;" ::: "memory");
        mbar_expect_tx(mbar0, TILE_BYTES);
        bulk_ld(stAu, cur + (size_t)n0 * D, mbar0);
    }
    if (t < D) avS[t] = av[t];

    // ---- B fragments = Wq (full 64 e: 8 et x 8 kc x 2 = 128 regs) ----
    uint32_t B[8][8][2];
    #pragma unroll
    for (int et = 0; et < 8; et++) {
        int e = et * 8 + lr;
        #pragma unroll
        for (int kc = 0; kc < 8; kc++) {
            B[et][kc][0] = f2tf32(Wq[e * 64 + kc * 8 + ci]);
            B[et][kc][1] = f2tf32(Wq[e * 64 + kc * 8 + ci + 4]);
        }
    }

    __syncthreads();                  // mbar init + avS visible
    if (lane == 0) { mbar_wait(mbar0, 0); }
    __syncthreads();                  // cur staging visible CTA-wide
    transform_tile(stagA, tileU, t, c);
    __syncthreads();                  // tileU (cur) ready; stagA free

    if (t == 0) {                     // stage h0, h1
        mbar_expect_tx(mbar0, TILE_BYTES);
        bulk_ld(stAu, hist + (size_t)n0 * D, mbar0);
        mbar_expect_tx(mbar1, TILE_BYTES);
        bulk_ld(stBu, hist + ((size_t)NTOT + n0) * D, mbar1);
    }

    // ---- Q prologue: full-e MMA on cur tile, park in qfS (warp-private) ----
    {
        uint4 qa[4], qb[4];
        #pragma unroll
        for (int j = 0; j < 4; j++) {
            qa[j] = *reinterpret_cast<const uint4*>(&tileU[fbA[j]]);
            qb[j] = *reinterpret_cast<const uint4*>(&tileU[fbA[j] + 512]);
        }
        #pragma unroll
        for (int et = 0; et < 8; et++) {
            float b0v = bq[et * 8 + 2 * ci]     + bk[et * 8 + 2 * ci];
            float b1v = bq[et * 8 + 2 * ci + 1] + bk[et * 8 + 2 * ci + 1];
            float c0 = b0v, c1 = b1v, c2 = b0v, c3 = b1v;
            #pragma unroll
            for (int j = 0; j < 4; j++) {
                if ((j & 1) == 0) {
                    mma_tf32(c0,c1,c2,c3, qa[j].x,qb[j].x,qa[j].y,qb[j].y, B[et][2*j][0],   B[et][2*j][1]);
                    mma_tf32(c0,c1,c2,c3, qa[j].z,qb[j].z,qa[j].w,qb[j].w, B[et][2*j+1][0], B[et][2*j+1][1]);
                } else {
                    mma_tf32(c0,c1,c2,c3, qa[j].z,qb[j].z,qa[j].w,qb[j].w, B[et][2*j][0],   B[et][2*j][1]);
                    mma_tf32(c0,c1,c2,c3, qa[j].x,qb[j].x,qa[j].y,qb[j].y, B[et][2*j+1][0], B[et][2*j+1][1]);
                }
            }
            qfS[(w * 8 + et) * 32 + lane] = make_float4(c0, c1, c2, c3);
        }
    }

    // ---- swap B fragments to Wk ----
    #pragma unroll
    for (int et = 0; et < 8; et++) {
        int e = et * 8 + lr;
        #pragma unroll
        for (int kc = 0; kc < 8; kc++) {
            B[et][kc][0] = f2tf32(Wk[e * 64 + kc * 8 + ci]);
            B[et][kc][1] = f2tf32(Wk[e * 64 + kc * 8 + ci + 4]);
        }
    }

    float accR[2][4][4];
    #pragma unroll
    for (int jj = 0; jj < 2; jj++)
        #pragma unroll
        for (int cc = 0; cc < 4; cc++)
            #pragma unroll
            for (int p = 0; p < 4; p++) accR[jj][cc][p] = 0.f;
    float sreg = 0.f;
    int ph0 = 1, ph1 = 0;

    const int srcl = ((lane >> 1) & 7) << 2;   // lane holding my token's logit

    for (int h = 0; h < HTOT; h++) {
        if (lane == 0) {
            if (h & 1) { mbar_wait(mbar1, ph1); } else { mbar_wait(mbar0, ph0); }
        }
        if (h & 1) ph1 ^= 1; else ph0 ^= 1;
        __syncthreads();              // staging visible; prev RMW done with tileU
        transform_tile((h & 1) ? stagB : stagA, tileU, t, c);
        __syncthreads();              // tileU ready; staging consumed

        if (h + 2 < HTOT && t == 0) {
            uint32_t mb   = (h & 1) ? mbar1 : mbar0;
            uint32_t sdst = (h & 1) ? stBu : stAu;
            mbar_expect_tx(mb, TILE_BYTES);
            bulk_ld(sdst, hist + ((size_t)(h + 2) * NTOT + n0) * D, mb);
        }

        // ---- warp-autonomous: full-e K-MMA + tanh logit, no more barriers ----
        uint4 qa[4], qb[4];
        #pragma unroll
        for (int j = 0; j < 4; j++) {
            qa[j] = *reinterpret_cast<const uint4*>(&tileU[fbA[j]]);
            qb[j] = *reinterpret_cast<const uint4*>(&tileU[fbA[j] + 512]);
        }
        float p_lo = 0.f, p_hi = 0.f;
        #pragma unroll
        for (int et = 0; et < 8; et++) {
            float4 q4 = qfS[(w * 8 + et) * 32 + lane];
            float c0 = q4.x, c1 = q4.y, c2 = q4.z, c3 = q4.w;
            #pragma unroll
            for (int j = 0; j < 4; j++) {
                if ((j & 1) == 0) {
                    mma_tf32(c0,c1,c2,c3, qa[j].x,qb[j].x,qa[j].y,qb[j].y, B[et][2*j][0],   B[et][2*j][1]);
                    mma_tf32(c0,c1,c2,c3, qa[j].z,qb[j].z,qa[j].w,qb[j].w, B[et][2*j+1][0], B[et][2*j+1][1]);
                } else {
                    mma_tf32(c0,c1,c2,c3, qa[j].z,qb[j].z,qa[j].w,qb[j].w, B[et][2*j][0],   B[et][2*j][1]);
                    mma_tf32(c0,c1,c2,c3, qa[j].x,qb[j].x,qa[j].y,qb[j].y, B[et][2*j+1][0], B[et][2*j+1][1]);
                }
            }
            float a0 = avS[et * 8 + 2 * ci];
            float a1 = avS[et * 8 + 2 * ci + 1];
            p_lo = fmaf(poly_tanh(c0), a0, fmaf(poly_tanh(c1), a1, p_lo));
            p_hi = fmaf(poly_tanh(c2), a0, fmaf(poly_tanh(c3), a1, p_hi));
        }
        // reduce over the 4 ci lanes -> full logits for tokens Tg+lr, Tg+lr+8
        p_lo += __shfl_xor_sync(0xffffffffu, p_lo, 1);
        p_lo += __shfl_xor_sync(0xffffffffu, p_lo, 2);
        p_hi += __shfl_xor_sync(0xffffffffu, p_hi, 1);
        p_hi += __shfl_xor_sync(0xffffffffu, p_hi, 2);
        float pe_lo = __expf(p_lo);
        float pe_hi = __expf(p_hi);
        // fetch my RMW token's weight (warp-local)
        float a = __shfl_sync(0xffffffffu, pe_lo, srcl);
        float b = __shfl_sync(0xffffffffu, pe_hi, srcl);
        float pe = (lane < 16) ? a : b;
        sreg += pe;
        // register RMW from tileU (valid until next transform)
        #pragma unroll
        for (int jj = 0; jj < 2; jj++)
            #pragma unroll
            for (int cc = 0; cc < 4; cc++) {
                float4 t4 = *reinterpret_cast<const float4*>(&tileU[roff[jj][cc]]);
                accR[jj][cc][0] = fmaf(pe, t4.x, accR[jj][cc][0]);
                accR[jj][cc][1] = fmaf(pe, t4.y, accR[jj][cc][1]);
                accR[jj][cc][2] = fmaf(pe, t4.z, accR[jj][cc][2]);
                accR[jj][cc][3] = fmaf(pe, t4.w, accR[jj][cc][3]);
            }
    }

    // ---- epilogue: ws = acc/s ; context = tanh(sc*|ws|/2)/(sc*|ws|) * ws ----
    float sinv = __fdividef(1.f, sreg);
    float ssq = 0.f;
    #pragma unroll
    for (int jj = 0; jj < 2; jj++)
        #pragma unroll
        for (int cc = 0; cc < 4; cc++)
            #pragma unroll
            for (int p = 0; p < 4; p++)
                ssq = fmaf(accR[jj][cc][p], accR[jj][cc][p], ssq);
    ssq += __shfl_xor_sync(0xffffffffu, ssq, 1);   // combine the two d-halves

    float sc = sqrtf(c);
    float r = sqrtf(ssq) * sinv;
    float u = sc * r;
    float g;
    if (u > 1e-12f) {
        float e = __expf(u);
        g = __fdividef(e - 1.f, (e + 1.f) * u);    // tanh(u/2)/u
    } else {
        g = 0.5f;
    }
    float f = g * sinv;

    float4* op = reinterpret_cast<float4*>(out + (size_t)(n0 + Tm) * D + hh * 32);
    #pragma unroll
    for (int gi = 0; gi < 8; gi++) {
        int jj  = gi >> 2;
        int pos = (gi & 3) ^ (jj << 1);
        float4 o;
        o.x = accR[jj][0][pos] * f;
        o.y = accR[jj][1][pos] * f;
        o.z = accR[jj][2][pos] * f;
        o.w = accR[jj][3][pos] * f;
        op[gi] = o;
    }
}

extern "C" void kernel_launch(void* const* d_in, const int* in_sizes, int n_in,
                              void* d_out, int out_size) {
    const float* cur  = (const float*)d_in[0];
    const float* hist = (const float*)d_in[1];
    const float* curv = (const float*)d_in[2];
    const float* Wq   = (const float*)d_in[3];
    const float* bq   = (const float*)d_in[4];
    const float* Wk   = (const float*)d_in[5];
    const float* bk   = (const float*)d_in[6];
    const float* av   = (const float*)d_in[7];
    float* o = (float*)d_out;

    const int smem_bytes = (32832 + 8) * sizeof(float);
    cudaFuncSetAttribute(hyp_attn_kernel,
                         cudaFuncAttributeMaxDynamicSharedMemorySize, smem_bytes);
    hyp_attn_kernel<<<NTOT / NT, NTHREADS, smem_bytes>>>(
        cur, hist, curv, Wq, bq, Wk, bk, av, o);
}

// round 13
// speedup vs baseline: 1.0542x; 1.0542x over previous
#include <cuda_runtime.h>
#include <math.h>
#include <stdint.h>

#define NTOT 32768
#define HTOT 32
#define D    64
#define NT   128
#define NTHREADS 512
#define TILE_BYTES (NT * D * 4)   // 32768

// ---------- tf32 helpers ----------
__device__ __forceinline__ uint32_t f2tf32(float f) {
    uint32_t u;
    asm("cvt.rna.tf32.f32 %0, %1;" : "=r"(u) : "f"(f));
    return u;
}

__device__ __forceinline__ void mma_tf32(float& c0, float& c1, float& c2, float& c3,
                                         uint32_t a0, uint32_t a1, uint32_t a2, uint32_t a3,
                                         uint32_t b0, uint32_t b1) {
    asm volatile(
        "mma.sync.aligned.m16n8k8.row.col.f32.tf32.tf32.f32 "
        "{%0,%1,%2,%3}, {%4,%5,%6,%7}, {%8,%9}, {%0,%1,%2,%3};"
        : "+f"(c0), "+f"(c1), "+f"(c2), "+f"(c3)
        : "r"(a0), "r"(a1), "r"(a2), "r"(a3), "r"(b0), "r"(b1));
}

__device__ __forceinline__ float poly_tanh(float x) {
    float t = x * x;
    float p = fmaf(t, -0.05396825397f, 0.13333333333f);
    p = fmaf(t, p, -0.33333333333f);
    return fmaf(x * t, p, x);
}

__device__ __forceinline__ float logscale_from_ssq(float ssq, float c) {
    float t = c * ssq;
    float p = fmaf(t, 0.22222222f, 0.28571429f);
    p = fmaf(t, p, 0.4f);
    p = fmaf(t, p, 0.66666667f);
    return fmaf(t, p, 2.0f);
}

// Fragment-native swizzled tile layout (conflict-free; rounds 3-10).
__device__ __forceinline__ int chunk_off(int token, int ci, int j) {
    int pb = (token >> 1) & 1;
    int b2 = (token >> 2) & 1;
    int jl = j & 1;
    int j1 = (j >> 1) & 1;
    int slot = ((token & 1) << 2) | (ci ^ (jl ^ pb) ^ ((j1 ^ b2) << 1));
    return ((token >> 1) << 7) | (j << 5) | (slot << 2);
}

// ---------- TMA bulk copy + mbarrier (proven rounds 7-10) ----------
__device__ __forceinline__ void mbar_init(uint32_t mbar, uint32_t cnt) {
    asm volatile("mbarrier.init.shared.b64 [%0], %1;" :: "r"(mbar), "r"(cnt) : "memory");
}
__device__ __forceinline__ void mbar_expect_tx(uint32_t mbar, uint32_t bytes) {
    asm volatile("mbarrier.arrive.expect_tx.shared.b64 _, [%0], %1;"
                 :: "r"(mbar), "r"(bytes) : "memory");
}
__device__ __forceinline__ void bulk_ld(uint32_t sdst, const void* gsrc, uint32_t mbar) {
    asm volatile(
        "cp.async.bulk.shared::cta.global.mbarrier::complete_tx::bytes [%0], [%1], %2, [%3];"
        :: "r"(sdst), "l"(gsrc), "r"((uint32_t)TILE_BYTES), "r"(mbar) : "memory");
}
__device__ __forceinline__ void mbar_wait(uint32_t mbar, uint32_t parity) {
    uint32_t done;
    asm volatile(
        "{\n\t.reg .pred p;\n\t"
        "mbarrier.try_wait.parity.acquire.cta.shared::cta.b64 p, [%1], %2;\n\t"
        "selp.b32 %0, 1, 0, p;\n\t}"
        : "=r"(done) : "r"(mbar), "r"(parity) : "memory");
    if (!done) {
        asm volatile(
            "{\n\t.reg .pred P1;\n\t"
            "WAIT_LOOP_%=:\n\t"
            "mbarrier.try_wait.parity.acquire.cta.shared::cta.b64 P1, [%0], %1, 0x989680;\n\t"
            "@P1 bra.uni WAIT_DONE_%=;\n\t"
            "bra.uni WAIT_LOOP_%=;\n\t"
            "WAIT_DONE_%=:\n\t}"
            :: "r"(mbar), "r"(parity) : "memory");
    }
}

// permute-only transform: raw fp32 staging -> swizzled tf32 tile (no norms)
__device__ __forceinline__ void transform_tile(const float* __restrict__ stag,
                                               uint32_t* __restrict__ tileU,
                                               int pt) {
    const float4* s4 = reinterpret_cast<const float4*>(stag);
    const int col4 = pt & 15;
    const int rgrp = pt >> 4;         // 0..31
    const int j    = col4 >> 2;
    const int posR = col4 & 3;
    const int posP = posR ^ ((j & 1) << 1);
    int base[4];
    #pragma unroll
    for (int ci = 0; ci < 4; ci++)
        base[ci] = chunk_off(rgrp, ci, j) + posP;

    #pragma unroll
    for (int jj = 0; jj < 4; jj++) {
        float4 v = s4[pt + 512 * jj];
        int o = jj << 11;             // +32 rows = +2048 floats
        tileU[base[0] + o] = f2tf32(v.x);
        tileU[base[1] + o] = f2tf32(v.y);
        tileU[base[2] + o] = f2tf32(v.z);
        tileU[base[3] + o] = f2tf32(v.w);
    }
}

// norm pass: thread t owns token t>>2, d-quarter t&3; returns log-map scale
// (same token map as the RMW, so the scale stays in-register there).
__device__ __forceinline__ float norm_pass(const float* __restrict__ stag,
                                           float* __restrict__ scaleS,
                                           int t, float c) {
    const float4* s4 = reinterpret_cast<const float4*>(stag);
    const int token = t >> 2;
    const int dq    = t & 3;
    float ssq = 0.f;
    #pragma unroll
    for (int k = 0; k < 4; k++) {
        float4 v = s4[token * 16 + dq * 4 + k];
        ssq = fmaf(v.x, v.x, fmaf(v.y, v.y, fmaf(v.z, v.z, fmaf(v.w, v.w, ssq))));
    }
    ssq += __shfl_xor_sync(0xffffffffu, ssq, 1);
    ssq += __shfl_xor_sync(0xffffffffu, ssq, 2);
    float s = logscale_from_ssq(ssq, c);
    if (dq == 0) scaleS[token] = s;
    return s;
}

__global__ __launch_bounds__(NTHREADS, 1)
void hyp_attn_kernel(const float* __restrict__ cur,
                     const float* __restrict__ hist,
                     const float* __restrict__ curv,
                     const float* __restrict__ Wq,
                     const float* __restrict__ bq,
                     const float* __restrict__ Wk,
                     const float* __restrict__ bk,
                     const float* __restrict__ av,
                     float* __restrict__ out) {
    extern __shared__ float sm[];
    uint32_t* tileU = reinterpret_cast<uint32_t*>(sm);   // 8192 u32
    float* stagA  = sm + 8192;                           // 8192
    float* stagB  = sm + 16384;                          // 8192
    float4* qfS   = reinterpret_cast<float4*>(sm + 24576);// 2048 float4
    float* lp     = sm + 32768;                          // 256
    float* scaleS = sm + 33024;                          // 128
    float* avS    = sm + 33152;                          // 64
    uint32_t mbarBase = (uint32_t)__cvta_generic_to_shared(sm + 33216);

    const int t    = threadIdx.x;
    const int lane = t & 31;
    const int w    = t >> 5;          // 0..15
    const int n0   = blockIdx.x * NT;
    const float c  = curv[0];

    const uint32_t mbar0 = mbarBase;
    const uint32_t mbar1 = mbarBase + 8;
    const uint32_t stAu = (uint32_t)__cvta_generic_to_shared(stagA);
    const uint32_t stBu = (uint32_t)__cvta_generic_to_shared(stagB);

    // warp roles: token group tg = w&7 (16 tokens), e-half eh = w>>3 (32 e)
    const int tg = w & 7;
    const int eh = w >> 3;
    const int Tg = tg * 16;
    const int E0 = eh * 32;
    const int lr = lane >> 2;         // 0..7
    const int ci = lane & 3;

    // A-fragment bases for token Tg+lr (token +8 is +512 u32)
    int fbA[4];
    #pragma unroll
    for (int j = 0; j < 4; j++) fbA[j] = chunk_off(Tg + lr, ci, j);

    // RMW ownership: token = t>>2, d-quarter dq = t&3 (16 floats)
    const int tok = t >> 2;
    const int dq  = t & 3;
    int roff[4];
    #pragma unroll
    for (int cc = 0; cc < 4; cc++) roff[cc] = chunk_off(tok, cc, dq);

    // ---- TMA: first load (current tile) ----
    if (t == 0) {
        mbar_init(mbar0, 1);
        mbar_init(mbar1, 1);
        asm volatile("fence.proxy.async.shared::cta;" ::: "memory");
        mbar_expect_tx(mbar0, TILE_BYTES);
        bulk_ld(stAu, cur + (size_t)n0 * D, mbar0);
    }
    if (t < D) avS[t] = av[t];

    // ---- B fragments = Wq for this e-half: 4 et x 8 kc x 2 = 64 regs ----
    uint32_t B[4][8][2];
    #pragma unroll
    for (int et = 0; et < 4; et++) {
        int e = E0 + et * 8 + lr;
        #pragma unroll
        for (int kc = 0; kc < 8; kc++) {
            B[et][kc][0] = f2tf32(Wq[e * 64 + kc * 8 + ci]);
            B[et][kc][1] = f2tf32(Wq[e * 64 + kc * 8 + ci + 4]);
        }
    }

    __syncthreads();                  // mbar init + avS visible
    if (lane == 0) { mbar_wait(mbar0, 0); }
    __syncthreads();                  // cur staging visible CTA-wide
    norm_pass(stagA, scaleS, t, c);   // scaleS = cur scales
    transform_tile(stagA, tileU, t);
    __syncthreads();                  // tileU(cur) + scaleS ready; stagA free

    if (t == 0) {                     // stage h0, h1
        mbar_expect_tx(mbar0, TILE_BYTES);
        bulk_ld(stAu, hist + (size_t)n0 * D, mbar0);
        mbar_expect_tx(mbar1, TILE_BYTES);
        bulk_ld(stBu, hist + ((size_t)NTOT + n0) * D, mbar1);
    }

    // ---- Q prologue: C = cur_tile x Wq^T ; qf = scale*C + bq + bk -> qfS ----
    {
        float C0[4], C1[4], C2[4], C3[4];
        #pragma unroll
        for (int et = 0; et < 4; et++) { C0[et]=0.f; C1[et]=0.f; C2[et]=0.f; C3[et]=0.f; }
        #pragma unroll
        for (int j = 0; j < 4; j++) {
            uint4 qa = *reinterpret_cast<const uint4*>(&tileU[fbA[j]]);
            uint4 qb = *reinterpret_cast<const uint4*>(&tileU[fbA[j] + 512]);
            #pragma unroll
            for (int et = 0; et < 4; et++) {
                if ((j & 1) == 0) {
                    mma_tf32(C0[et],C1[et],C2[et],C3[et], qa.x,qb.x,qa.y,qb.y, B[et][2*j][0],   B[et][2*j][1]);
                    mma_tf32(C0[et],C1[et],C2[et],C3[et], qa.z,qb.z,qa.w,qb.w, B[et][2*j+1][0], B[et][2*j+1][1]);
                } else {
                    mma_tf32(C0[et],C1[et],C2[et],C3[et], qa.z,qb.z,qa.w,qb.w, B[et][2*j][0],   B[et][2*j][1]);
                    mma_tf32(C0[et],C1[et],C2[et],C3[et], qa.x,qb.x,qa.y,qb.y, B[et][2*j+1][0], B[et][2*j+1][1]);
                }
            }
        }
        float s_lo = scaleS[Tg + lr];
        float s_hi = scaleS[Tg + lr + 8];
        #pragma unroll
        for (int et = 0; et < 4; et++) {
            float b0v = bq[E0 + et * 8 + 2 * ci]     + bk[E0 + et * 8 + 2 * ci];
            float b1v = bq[E0 + et * 8 + 2 * ci + 1] + bk[E0 + et * 8 + 2 * ci + 1];
            float4 q4;
            q4.x = fmaf(s_lo, C0[et], b0v);
            q4.y = fmaf(s_lo, C1[et], b1v);
            q4.z = fmaf(s_hi, C2[et], b0v);
            q4.w = fmaf(s_hi, C3[et], b1v);
            qfS[(w * 4 + et) * 32 + lane] = q4;
        }
    }

    // ---- swap B fragments to Wk ----
    #pragma unroll
    for (int et = 0; et < 4; et++) {
        int e = E0 + et * 8 + lr;
        #pragma unroll
        for (int kc = 0; kc < 8; kc++) {
            B[et][kc][0] = f2tf32(Wk[e * 64 + kc * 8 + ci]);
            B[et][kc][1] = f2tf32(Wk[e * 64 + kc * 8 + ci + 4]);
        }
    }

    float accR[4][4];
    #pragma unroll
    for (int cc = 0; cc < 4; cc++)
        #pragma unroll
        for (int p = 0; p < 4; p++) accR[cc][p] = 0.f;
    float sreg = 0.f;
    int ph0 = 1, ph1 = 0;

    for (int h = 0; h < HTOT; h++) {
        if (lane == 0) {
            if (h & 1) { mbar_wait(mbar1, ph1); } else { mbar_wait(mbar0, ph0); }
        }
        if (h & 1) ph1 ^= 1; else ph0 ^= 1;
        __syncthreads();              // staging visible; prev RMW done with tileU
        const float* stg = (h & 1) ? stagB : stagA;
        float scaleReg = norm_pass(stg, scaleS, t, c);   // my RMW token's scale
        transform_tile(stg, tileU, t);
        __syncthreads();              // tileU + scaleS ready; staging consumed

        if (h + 2 < HTOT && t == 0) {
            uint32_t mb   = (h & 1) ? mbar1 : mbar0;
            uint32_t sdst = (h & 1) ? stBu : stAu;
            mbar_expect_tx(mb, TILE_BYTES);
            bulk_ld(sdst, hist + ((size_t)(h + 2) * NTOT + n0) * D, mb);
        }

        // ---- K-MMA (16 tokens x 32 e) + post-scale tanh logit ----
        {
            float C0[4], C1[4], C2[4], C3[4];
            #pragma unroll
            for (int et = 0; et < 4; et++) { C0[et]=0.f; C1[et]=0.f; C2[et]=0.f; C3[et]=0.f; }
            #pragma unroll
            for (int j = 0; j < 4; j++) {
                uint4 qa = *reinterpret_cast<const uint4*>(&tileU[fbA[j]]);
                uint4 qb = *reinterpret_cast<const uint4*>(&tileU[fbA[j] + 512]);
                #pragma unroll
                for (int et = 0; et < 4; et++) {
                    if ((j & 1) == 0) {
                        mma_tf32(C0[et],C1[et],C2[et],C3[et], qa.x,qb.x,qa.y,qb.y, B[et][2*j][0],   B[et][2*j][1]);
                        mma_tf32(C0[et],C1[et],C2[et],C3[et], qa.z,qb.z,qa.w,qb.w, B[et][2*j+1][0], B[et][2*j+1][1]);
                    } else {
                        mma_tf32(C0[et],C1[et],C2[et],C3[et], qa.z,qb.z,qa.w,qb.w, B[et][2*j][0],   B[et][2*j][1]);
                        mma_tf32(C0[et],C1[et],C2[et],C3[et], qa.x,qb.x,qa.y,qb.y, B[et][2*j+1][0], B[et][2*j+1][1]);
                    }
                }
            }
            float s_lo = scaleS[Tg + lr];
            float s_hi = scaleS[Tg + lr + 8];
            float p_lo = 0.f, p_hi = 0.f;
            #pragma unroll
            for (int et = 0; et < 4; et++) {
                float4 q4 = qfS[(w * 4 + et) * 32 + lane];
                float a0 = avS[E0 + et * 8 + 2 * ci];
                float a1 = avS[E0 + et * 8 + 2 * ci + 1];
                float t0 = poly_tanh(fmaf(s_lo, C0[et], q4.x));
                float t1 = poly_tanh(fmaf(s_lo, C1[et], q4.y));
                float t2 = poly_tanh(fmaf(s_hi, C2[et], q4.z));
                float t3 = poly_tanh(fmaf(s_hi, C3[et], q4.w));
                p_lo = fmaf(t0, a0, fmaf(t1, a1, p_lo));
                p_hi = fmaf(t2, a0, fmaf(t3, a1, p_hi));
            }
            p_lo += __shfl_xor_sync(0xffffffffu, p_lo, 1);
            p_lo += __shfl_xor_sync(0xffffffffu, p_lo, 2);
            p_hi += __shfl_xor_sync(0xffffffffu, p_hi, 1);
            p_hi += __shfl_xor_sync(0xffffffffu, p_hi, 2);
            if (ci == 0) {
                lp[eh * 128 + Tg + lr]     = p_lo;
                lp[eh * 128 + Tg + lr + 8] = p_hi;
            }
        }
        __syncthreads();              // lp ready

        // softmax accumulation + register RMW (scale folded into weight)
        float L  = lp[tok] + lp[128 + tok];
        float pe = __expf(L);         // logits bounded << 88
        sreg += pe;
        float pw = pe * scaleReg;     // acc += pe * scale * x_raw
        #pragma unroll
        for (int cc = 0; cc < 4; cc++) {
            float4 t4 = *reinterpret_cast<const float4*>(&tileU[roff[cc]]);
            accR[cc][0] = fmaf(pw, t4.x, accR[cc][0]);
            accR[cc][1] = fmaf(pw, t4.y, accR[cc][1]);
            accR[cc][2] = fmaf(pw, t4.z, accR[cc][2]);
            accR[cc][3] = fmaf(pw, t4.w, accR[cc][3]);
        }
    }

    // ---- epilogue: ws = acc/s ; context = tanh(sc*|ws|/2)/(sc*|ws|) * ws ----
    float sinv = __fdividef(1.f, sreg);
    float ssq = 0.f;
    #pragma unroll
    for (int cc = 0; cc < 4; cc++)
        #pragma unroll
        for (int p = 0; p < 4; p++)
            ssq = fmaf(accR[cc][p], accR[cc][p], ssq);
    ssq += __shfl_xor_sync(0xffffffffu, ssq, 1);
    ssq += __shfl_xor_sync(0xffffffffu, ssq, 2);

    float sc = sqrtf(c);
    float r = sqrtf(ssq) * sinv;
    float u = sc * r;
    float g;
    if (u > 1e-12f) {
        float e = __expf(u);
        g = __fdividef(e - 1.f, (e + 1.f) * u);    // tanh(u/2)/u
    } else {
        g = 0.5f;
    }
    float f = g * sinv;

    const int xo = (dq & 1) << 1;     // posP = posR ^ ((j&1)<<1)
    float4* op = reinterpret_cast<float4*>(out + (size_t)(n0 + tok) * D + dq * 16);
    #pragma unroll
    for (int gi = 0; gi < 4; gi++) {
        int pos = gi ^ xo;
        float4 o;
        o.x = accR[0][pos] * f;
        o.y = accR[1][pos] * f;
        o.z = accR[2][pos] * f;
        o.w = accR[3][pos] * f;
        op[gi] = o;
    }
}

extern "C" void kernel_launch(void* const* d_in, const int* in_sizes, int n_in,
                              void* d_out, int out_size) {
    const float* cur  = (const float*)d_in[0];
    const float* hist = (const float*)d_in[1];
    const float* curv = (const float*)d_in[2];
    const float* Wq   = (const float*)d_in[3];
    const float* bq   = (const float*)d_in[4];
    const float* Wk   = (const float*)d_in[5];
    const float* bk   = (const float*)d_in[6];
    const float* av   = (const float*)d_in[7];
    float* o = (float*)d_out;

    const int smem_bytes = (33216 + 8) * sizeof(float);
    cudaFuncSetAttribute(hyp_attn_kernel,
                         cudaFuncAttributeMaxDynamicSharedMemorySize, smem_bytes);
    hyp_attn_kernel<<<NTOT / NT, NTHREADS, smem_bytes>>>(
        cur, hist, curv, Wq, bq, Wk, bk, av, o);
}